// round 13
// baseline (speedup 1.0000x reference)
#include <cuda_runtime.h>
#include <cstdint>

// ---------------------------------------------------------------------------
// GCN layer on GB300 (plain compute_103 PTX -> legacy mma.sync tf32 path):
//   d[i]  = rsqrt(1 + #{j : A[i][j] > 1e-15})
//   g     = diag(d) @ (x @ W^T)                      [8192,256]
//   out   = relu( diag(d) @ (A @ g + g) )            [8192,256]
//   output buffer = [ out (8192*256 f32) | verbatim copy of A (8192^2 f32) ]
//
// k0x/k0w: rna-round x; round + interleave W; zero stream-K counters
// K1: degrees only (DRAM roofline)
// K2: tf32 MMA linear; epilogue applies d, emits g_h + interleaved g_gT
// K3: STREAM-K tf32 GEMM over 148 CTAs: global unit space = 128 tiles x 256
//     k-chunks; each CTA owns a contiguous range (statically partitioned).
//     Partial tiles stored to fixed slots; last arriver merges in slot order
//     (bit-deterministic) and runs the epilogue. A copy rides with units.
// ---------------------------------------------------------------------------

#define EPSV 1e-15f

static constexpr int NN = 8192;   // nodes
static constexpr int DF = 256;    // feature dim (in == out)

// shared GEMM tiling (K3 and K2-MMA)
static constexpr int BK = 32;                        // K elems per stage
static constexpr int NCHUNK2 = DF / BK;              // 8   (K2)
static constexpr int STAGES = 4;
static constexpr int LDSA = 36;   // A smem row stride (floats): ldmatrix conflict-free
static constexpr int LDSB = 48;   // B smem row stride (floats): LDS.128 conflict-free
static constexpr int A_TILE_FLOATS = 128 * LDSA;     // 4608
static constexpr int B_TILE_FLOATS = 128 * LDSB;     // 6144
static constexpr int STAGE_FLOATS  = A_TILE_FLOATS + B_TILE_FLOATS;  // 10752
static constexpr int SMEM_BYTES    = STAGES * STAGE_FLOATS * 4;      // 172032
static constexpr int LT = 133;    // K2 transpose buffer stride

// stream-K geometry: 128 output tiles (64 m x 2 c) x 256 k-chunks
static constexpr int NTILE = 128;
static constexpr int UNITS = NTILE * 256;            // 32768
static constexpr int NCTA3 = 148;
static constexpr int UBASE = UNITS / NCTA3;          // 221
static constexpr int UREM  = UNITS % NCTA3;          // 60

// scratch (static device arrays: allocation-free)
__device__ __align__(128) float g_gT[(size_t)DF * NN];  // tf32-rounded, interleaved g^T
__device__ __align__(128) float g_h [(size_t)NN * DF];  // g [8192][256] (for +I term)
__device__ __align__(128) float g_xr[(size_t)NN * DF];  // rna-rounded x
__device__ __align__(128) float g_Wr[(size_t)DF * DF];  // rounded + interleaved W
__device__ __align__(128) float g_part[(size_t)NTILE * 3 * 16384]; // partial tiles
__device__ int   g_cnt[NTILE];                           // per-tile chunk counters
__device__ float g_d[NN];

// ---------------------------------------------------------------------------
// PTX helpers (plain sm_80+ PTX only: safe for non-'a' target)
// ---------------------------------------------------------------------------
__device__ __forceinline__ uint32_t smem_u32(const void* p) {
    uint32_t a;
    asm("{ .reg .u64 t; cvta.to.shared.u64 t, %1; cvt.u32.u64 %0, t; }"
        : "=r"(a) : "l"(p));
    return a;
}

__device__ __forceinline__ void cp_async16(uint32_t dst, const void* src) {
    asm volatile("cp.async.cg.shared.global [%0], [%1], 16;"
                 :: "r"(dst), "l"(src));
}
#define CP_COMMIT() asm volatile("cp.async.commit_group;" ::: "memory")
#define CP_WAIT2()  asm volatile("cp.async.wait_group 2;" ::: "memory")

__device__ __forceinline__ uint32_t f2tf32(float f) {
    uint32_t r;
    asm("cvt.rna.tf32.f32 %0, %1;" : "=r"(r) : "f"(f));
    return r;
}
__device__ __forceinline__ float rndf(float f) {
    return __uint_as_float(f2tf32(f));
}

__device__ __forceinline__ void ldsm_x4(uint32_t* r, uint32_t addr) {
    asm volatile("ldmatrix.sync.aligned.m8n8.x4.shared.b16 {%0,%1,%2,%3}, [%4];"
                 : "=r"(r[0]), "=r"(r[1]), "=r"(r[2]), "=r"(r[3])
                 : "r"(addr));
}

__device__ __forceinline__ void mma_tf32(float* d, const uint32_t* a,
                                         const uint32_t* b) {
    asm volatile(
        "mma.sync.aligned.m16n8k8.row.col.f32.tf32.tf32.f32 "
        "{%0,%1,%2,%3}, {%4,%5,%6,%7}, {%8,%9}, {%0,%1,%2,%3};"
        : "+f"(d[0]), "+f"(d[1]), "+f"(d[2]), "+f"(d[3])
        : "r"(a[0]), "r"(a[1]), "r"(a[2]), "r"(a[3]),
          "r"(b[0]), "r"(b[1]));
}

// stream-K partition helpers (pure formulas -> deterministic)
__device__ __forceinline__ int u_start(int r) {
    return UBASE * r + (r < UREM ? r : UREM);
}
__device__ __forceinline__ int r_of(int u) {
    return (u < (UBASE + 1) * UREM) ? u / (UBASE + 1) : (u - UREM) / UBASE;
}

// ---------------------------------------------------------------------------
// k0x: rna-round x into g_xr; also zero stream-K counters (every launch).
// ---------------------------------------------------------------------------
__global__ void __launch_bounds__(256) k0_round_x(const float* __restrict__ x) {
    if (blockIdx.x == 0 && threadIdx.x < NTILE) g_cnt[threadIdx.x] = 0;
    size_t i = ((size_t)blockIdx.x * 256 + threadIdx.x) * 8;
    float4 a = *reinterpret_cast<const float4*>(x + i);
    float4 b = *reinterpret_cast<const float4*>(x + i + 4);
    a.x = rndf(a.x); a.y = rndf(a.y); a.z = rndf(a.z); a.w = rndf(a.w);
    b.x = rndf(b.x); b.y = rndf(b.y); b.z = rndf(b.z); b.w = rndf(b.w);
    *reinterpret_cast<float4*>(g_xr + i)     = a;
    *reinterpret_cast<float4*>(g_xr + i + 4) = b;
}

// ---------------------------------------------------------------------------
// k0w: round W + 16-group interleave along k: stored[a*4+q] = v[a+4q].
// ---------------------------------------------------------------------------
__global__ void __launch_bounds__(32) k0_round_w(const float* __restrict__ W) {
    int c = blockIdx.x * 32 + threadIdx.x;
    const float4* src = reinterpret_cast<const float4*>(W + (size_t)c * DF);
    float4* dst = reinterpret_cast<float4*>(g_Wr + (size_t)c * DF);
    #pragma unroll
    for (int gq = 0; gq < 16; gq++) {
        float v[16];
        #pragma unroll
        for (int t = 0; t < 4; t++) {
            float4 q = src[gq * 4 + t];
            v[t * 4 + 0] = q.x; v[t * 4 + 1] = q.y;
            v[t * 4 + 2] = q.z; v[t * 4 + 3] = q.w;
        }
        #pragma unroll
        for (int a = 0; a < 4; a++) {
            float4 w;
            w.x = rndf(v[a]);     w.y = rndf(v[a + 4]);
            w.z = rndf(v[a + 8]); w.w = rndf(v[a + 12]);
            dst[gq * 4 + a] = w;
        }
    }
}

// ---------------------------------------------------------------------------
// K1: degrees only. One block per row: 256 threads x 8 float4 (read 256 MB).
// ---------------------------------------------------------------------------
__global__ void __launch_bounds__(256) k1_deg(const float* __restrict__ A) {
    int row = blockIdx.x;
    const float4* src = reinterpret_cast<const float4*>(A + (size_t)row * NN);
    int cnt = 0;
    #pragma unroll
    for (int i = 0; i < 8; i++) {
        float4 v = src[threadIdx.x + i * 256];
        cnt += (v.x > EPSV) + (v.y > EPSV) + (v.z > EPSV) + (v.w > EPSV);
    }
    #pragma unroll
    for (int o = 16; o > 0; o >>= 1) cnt += __shfl_down_sync(0xffffffffu, cnt, o);
    __shared__ int ws[8];
    if ((threadIdx.x & 31) == 0) ws[threadIdx.x >> 5] = cnt;
    __syncthreads();
    if (threadIdx.x == 0) {
        int t = 0;
        #pragma unroll
        for (int w = 0; w < 8; w++) t += ws[w];
        g_d[row] = rsqrtf(1.0f + (float)t);
    }
}

// ---------------------------------------------------------------------------
// K2 (tensor): h = x_r @ W_r^T ; g = d .* h.  (unchanged from R10)
// ---------------------------------------------------------------------------
__device__ __forceinline__ void k2_stage_load(uint32_t sbase, int s,
                                              const float* __restrict__ aSrc,
                                              const float* __restrict__ bSrc,
                                              int tid) {
    uint32_t stA = sbase + (uint32_t)(s * STAGE_FLOATS * 4);
    uint32_t stB = stA + (uint32_t)(A_TILE_FLOATS * 4);
    #pragma unroll
    for (int i = 0; i < 4; i++) {
        int e = tid + i * 256;
        int r = e >> 3, c = e & 7;
        cp_async16(stA + r * (LDSA * 4) + c * 16, aSrc + (size_t)r * DF + c * 4);
    }
    #pragma unroll
    for (int i = 0; i < 4; i++) {
        int e = tid + i * 256;
        int r = e >> 3, c = e & 7;
        cp_async16(stB + r * (LDSB * 4) + c * 16, bSrc + (size_t)r * DF + c * 4);
    }
}

__global__ void __launch_bounds__(256, 1) k2_mma() {
    extern __shared__ float smem[];
    uint32_t sbase = smem_u32(smem);
    int tid  = threadIdx.x;
    int lane = tid & 31;
    int wid  = tid >> 5;
    int warp_m = wid >> 2;
    int warp_n = wid & 3;
    int m0 = blockIdx.x * 128;
    int c0 = blockIdx.y * 128;

    float acc[4][4][4];
    #pragma unroll
    for (int mi = 0; mi < 4; mi++)
        #pragma unroll
        for (int ni = 0; ni < 4; ni++)
            #pragma unroll
            for (int q = 0; q < 4; q++) acc[mi][ni][q] = 0.0f;

    const float* aBase = g_xr + (size_t)m0 * DF;
    const float* bBase = g_Wr + (size_t)c0 * DF;

    #pragma unroll
    for (int s = 0; s < STAGES - 1; s++) {
        k2_stage_load(sbase, s, aBase + s * BK, bBase + s * BK, tid);
        CP_COMMIT();
    }

    int lm_row = ((lane >> 3) & 1) * 8 + (lane & 7);
    int lm_col = (lane >> 4) * 4;
    uint32_t a_lm_byte = (uint32_t)(((warp_m * 64 + lm_row) * LDSA + lm_col) * 4);
    uint32_t b_ld_f = (uint32_t)((warp_n * 32 + (lane >> 2)) * LDSB + (lane & 3) * 4);

    for (int kc = 0; kc < NCHUNK2; kc++) {
        CP_WAIT2();
        __syncthreads();
        uint32_t stA = sbase + (uint32_t)((kc & 3) * STAGE_FLOATS * 4);
        const float* Bs = smem + (kc & 3) * STAGE_FLOATS + A_TILE_FLOATS;

        #pragma unroll
        for (int kh = 0; kh < 2; kh++) {
            float4 bq[4];
            #pragma unroll
            for (int ni = 0; ni < 4; ni++)
                bq[ni] = *reinterpret_cast<const float4*>(
                    Bs + b_ld_f + ni * 8 * LDSB + kh * 16);
            #pragma unroll
            for (int kj = 0; kj < 2; kj++) {
                uint32_t af[4][4];
                uint32_t abase = stA + a_lm_byte + (uint32_t)((kh * 2 + kj) * 32);
                #pragma unroll
                for (int mi = 0; mi < 4; mi++)
                    ldsm_x4(af[mi], abase + (uint32_t)(mi * 16 * LDSA * 4));
                #pragma unroll
                for (int mi = 0; mi < 4; mi++)
                    #pragma unroll
                    for (int ni = 0; ni < 4; ni++) {
                        uint32_t bf[2];
                        bf[0] = __float_as_uint(kj ? bq[ni].z : bq[ni].x);
                        bf[1] = __float_as_uint(kj ? bq[ni].w : bq[ni].y);
                        mma_tf32(acc[mi][ni], af[mi], bf);
                    }
            }
        }
        int kl = kc + STAGES - 1;
        if (kl < NCHUNK2)
            k2_stage_load(sbase, kl & 3, aBase + kl * BK, bBase + kl * BK, tid);
        CP_COMMIT();
    }

    __syncthreads();
    float* tb = smem;
    #pragma unroll
    for (int mi = 0; mi < 4; mi++) {
        int r0l = warp_m * 64 + mi * 16 + (lane >> 2);
        int r1l = r0l + 8;
        float d0 = g_d[m0 + r0l], d1 = g_d[m0 + r1l];
        #pragma unroll
        for (int ni = 0; ni < 4; ni++) {
            int ccl = warp_n * 32 + ni * 8 + (lane & 3) * 2;
            float h00 = d0 * acc[mi][ni][0], h01 = d0 * acc[mi][ni][1];
            float h10 = d1 * acc[mi][ni][2], h11 = d1 * acc[mi][ni][3];
            float2 v0; v0.x = h00; v0.y = h01;
            float2 v1; v1.x = h10; v1.y = h11;
            *reinterpret_cast<float2*>(g_h + (size_t)(m0 + r0l) * DF + c0 + ccl) = v0;
            *reinterpret_cast<float2*>(g_h + (size_t)(m0 + r1l) * DF + c0 + ccl) = v1;
            tb[ccl * LT + r0l] = h00; tb[(ccl + 1) * LT + r0l] = h01;
            tb[ccl * LT + r1l] = h10; tb[(ccl + 1) * LT + r1l] = h11;
        }
    }
    __syncthreads();
    {
        int cl = tid >> 1;
        int jh = (tid & 1) * 64;
        const float* row = tb + cl * LT + jh;
        float4* dst = reinterpret_cast<float4*>(
            g_gT + (size_t)(c0 + cl) * NN + m0 + jh);
        #pragma unroll
        for (int q16 = 0; q16 < 4; q16++) {
            const float* v = row + q16 * 16;
            #pragma unroll
            for (int a = 0; a < 4; a++) {
                float4 w;
                w.x = rndf(v[a]);     w.y = rndf(v[a + 4]);
                w.z = rndf(v[a + 8]); w.w = rndf(v[a + 12]);
                dst[q16 * 4 + a] = w;
            }
        }
    }
}

// ---------------------------------------------------------------------------
// K3 stream-K: unit u -> tile t = u>>8 (m0=(t>>1)*128, c0=(t&1)*128),
// chunk kc = u&255.  148 CTAs x contiguous ranges.
// ---------------------------------------------------------------------------
__device__ __forceinline__ void k3_load_u(uint32_t sbase, int s, int u,
                                          const float* __restrict__ Aop,
                                          int tid) {
    int t = u >> 8, kc = u & 255;
    int m0 = (t >> 1) << 7;
    int c0 = (t & 1) << 7;
    const float* aSrc = Aop  + (size_t)m0 * NN + kc * BK;
    const float* bSrc = g_gT + (size_t)c0 * NN + kc * BK;
    uint32_t stA = sbase + (uint32_t)(s * STAGE_FLOATS * 4);
    uint32_t stB = stA + (uint32_t)(A_TILE_FLOATS * 4);
    #pragma unroll
    for (int i = 0; i < 4; i++) {
        int e = tid + i * 256;
        int r = e >> 3, c = e & 7;
        cp_async16(stA + r * (LDSA * 4) + c * 16, aSrc + (size_t)r * NN + c * 4);
    }
    #pragma unroll
    for (int i = 0; i < 4; i++) {
        int e = tid + i * 256;
        int r = e >> 3, c = e & 7;
        cp_async16(stB + r * (LDSB * 4) + c * 16, bSrc + (size_t)r * NN + c * 4);
    }
}

__global__ void __launch_bounds__(256, 1) k3_streamk(const float* __restrict__ Aop,
                                                     float* __restrict__ outp,
                                                     float* __restrict__ Acopy) {
    extern __shared__ float smem[];
    __shared__ int s_fin;
    uint32_t sbase = smem_u32(smem);
    int tid  = threadIdx.x;
    int lane = tid & 31;
    int wid  = tid >> 5;
    int warp_m = wid >> 2;
    int warp_n = wid & 3;
    int r = blockIdx.x;
    int u0 = u_start(r), uEnd = u_start(r + 1);

    float acc[4][4][4];
    #pragma unroll
    for (int mi = 0; mi < 4; mi++)
        #pragma unroll
        for (int ni = 0; ni < 4; ni++)
            #pragma unroll
            for (int q = 0; q < 4; q++) acc[mi][ni][q] = 0.0f;

    #pragma unroll
    for (int s = 0; s < STAGES - 1; s++) {
        k3_load_u(sbase, s, u0 + s, Aop, tid);
        CP_COMMIT();
    }

    int lm_row = ((lane >> 3) & 1) * 8 + (lane & 7);
    int lm_col = (lane >> 4) * 4;
    uint32_t a_lm_byte = (uint32_t)(((warp_m * 64 + lm_row) * LDSA + lm_col) * 4);
    uint32_t b_ld_f = (uint32_t)((warp_n * 32 + (lane >> 2)) * LDSB + (lane & 3) * 4);
    int cp_rl = tid >> 3;            // tile-local copy row 0..31
    int cp_c  = (tid & 7) * 4;

    int i = 0;
    for (int u = u0; u < uEnd; u++, i++) {
        CP_WAIT2();
        __syncthreads();
        int t  = u >> 8, kc = u & 255;
        int m0 = (t >> 1) << 7;
        int c0 = (t & 1) << 7;
        uint32_t stA = sbase + (uint32_t)((i & 3) * STAGE_FLOATS * 4);
        const float* As = smem + (i & 3) * STAGE_FLOATS;
        const float* Bs = As + A_TILE_FLOATS;

        // verbatim A copy: this c-half copies tile rows [(t&1)*64, +64)
        {
            int row = (t & 1) * 64 + cp_rl;
            float* dst = Acopy + (size_t)(m0 + row) * NN + kc * BK + cp_c;
            const float* s0 = As + row * LDSA + cp_c;
            float4 v0 = *reinterpret_cast<const float4*>(s0);
            float4 v1 = *reinterpret_cast<const float4*>(s0 + 32 * LDSA);
            *reinterpret_cast<float4*>(dst) = v0;
            *reinterpret_cast<float4*>(dst + (size_t)32 * NN) = v1;
        }

        #pragma unroll
        for (int kh = 0; kh < 2; kh++) {
            float4 bq[4];
            #pragma unroll
            for (int ni = 0; ni < 4; ni++)
                bq[ni] = *reinterpret_cast<const float4*>(
                    Bs + b_ld_f + ni * 8 * LDSB + kh * 16);
            #pragma unroll
            for (int kj = 0; kj < 2; kj++) {
                uint32_t af[4][4];
                uint32_t abase = stA + a_lm_byte + (uint32_t)((kh * 2 + kj) * 32);
                #pragma unroll
                for (int mi = 0; mi < 4; mi++)
                    ldsm_x4(af[mi], abase + (uint32_t)(mi * 16 * LDSA * 4));
                #pragma unroll
                for (int mi = 0; mi < 4; mi++)
                    #pragma unroll
                    for (int ni = 0; ni < 4; ni++) {
                        uint32_t bf[2];
                        bf[0] = __float_as_uint(kj ? bq[ni].z : bq[ni].x);
                        bf[1] = __float_as_uint(kj ? bq[ni].w : bq[ni].y);
                        mma_tf32(acc[mi][ni], af[mi], bf);
                    }
            }
        }

        if (u + 3 < uEnd) k3_load_u(sbase, (i + 3) & 3, u + 3, Aop, tid);
        CP_COMMIT();

        // portion flush at tile end or range end
        if (kc == 255 || u + 1 == uEnd) {
            int tu0 = t << 8;
            int pstart = (u0 > tu0) ? u0 : tu0;
            int nch = (u + 1) - pstart;
            int r0t = r_of(tu0);
            int slot = r - r0t;
            // store partial (layout: [frag 0..15][tid] as float4)
            float4* pb = reinterpret_cast<float4*>(
                g_part + ((size_t)t * 3 + slot) * 16384);
            #pragma unroll
            for (int mi = 0; mi < 4; mi++)
                #pragma unroll
                for (int ni = 0; ni < 4; ni++) {
                    float4 v;
                    v.x = acc[mi][ni][0]; v.y = acc[mi][ni][1];
                    v.z = acc[mi][ni][2]; v.w = acc[mi][ni][3];
                    pb[(mi * 4 + ni) * 256 + tid] = v;
                }
            __threadfence();
            __syncthreads();
            if (tid == 0)
                s_fin = (atomicAdd(&g_cnt[t], nch) + nch == 256) ? 1 : 0;
            __syncthreads();
            if (s_fin) {
                int nslot = r_of(tu0 + 255) - r0t + 1;
                const float4* base = reinterpret_cast<const float4*>(
                    g_part + (size_t)t * 3 * 16384);
                // deterministic merge: sum slots in fixed order
                #pragma unroll
                for (int mi = 0; mi < 4; mi++)
                    #pragma unroll
                    for (int ni = 0; ni < 4; ni++) {
                        float4 v = base[(mi * 4 + ni) * 256 + tid];
                        acc[mi][ni][0] = v.x; acc[mi][ni][1] = v.y;
                        acc[mi][ni][2] = v.z; acc[mi][ni][3] = v.w;
                    }
                for (int s2 = 1; s2 < nslot; s2++) {
                    #pragma unroll
                    for (int mi = 0; mi < 4; mi++)
                        #pragma unroll
                        for (int ni = 0; ni < 4; ni++) {
                            float4 v = base[s2 * 4096 + (mi * 4 + ni) * 256 + tid];
                            acc[mi][ni][0] += v.x; acc[mi][ni][1] += v.y;
                            acc[mi][ni][2] += v.z; acc[mi][ni][3] += v.w;
                        }
                }
                // epilogue: out = relu(d_i * (acc + g_i))
                #pragma unroll
                for (int mi = 0; mi < 4; mi++) {
                    int r0g = m0 + warp_m * 64 + mi * 16 + (lane >> 2);
                    int r1g = r0g + 8;
                    float d0 = g_d[r0g], d1 = g_d[r1g];
                    #pragma unroll
                    for (int ni = 0; ni < 4; ni++) {
                        int cc = c0 + warp_n * 32 + ni * 8 + (lane & 3) * 2;
                        float2 gh0 = *reinterpret_cast<const float2*>(
                            g_h + (size_t)r0g * DF + cc);
                        float2 gh1 = *reinterpret_cast<const float2*>(
                            g_h + (size_t)r1g * DF + cc);
                        float2 v0, v1;
                        v0.x = fmaxf(d0 * (acc[mi][ni][0] + gh0.x), 0.0f);
                        v0.y = fmaxf(d0 * (acc[mi][ni][1] + gh0.y), 0.0f);
                        v1.x = fmaxf(d1 * (acc[mi][ni][2] + gh1.x), 0.0f);
                        v1.y = fmaxf(d1 * (acc[mi][ni][3] + gh1.y), 0.0f);
                        *reinterpret_cast<float2*>(outp + (size_t)r0g * DF + cc) = v0;
                        *reinterpret_cast<float2*>(outp + (size_t)r1g * DF + cc) = v1;
                    }
                }
            }
            // reset accumulators for the next portion
            #pragma unroll
            for (int mi = 0; mi < 4; mi++)
                #pragma unroll
                for (int ni = 0; ni < 4; ni++)
                    #pragma unroll
                    for (int q = 0; q < 4; q++) acc[mi][ni][q] = 0.0f;
        }
    }
}

// ---------------------------------------------------------------------------
// launch
// ---------------------------------------------------------------------------
extern "C" void kernel_launch(void* const* d_in, const int* in_sizes, int n_in,
                              void* d_out, int out_size) {
    (void)in_sizes; (void)n_in; (void)out_size;
    const float* x = (const float*)d_in[0];
    const float* A = (const float*)d_in[1];
    const float* W = (const float*)d_in[2];
    float* out   = (float*)d_out;
    float* Acopy = out + (size_t)NN * DF;

    cudaFuncSetAttribute(k2_mma, cudaFuncAttributeMaxDynamicSharedMemorySize,
                         SMEM_BYTES);
    cudaFuncSetAttribute(k3_streamk, cudaFuncAttributeMaxDynamicSharedMemorySize,
                         SMEM_BYTES);

    k0_round_x<<<(NN * DF) / (256 * 8), 256>>>(x);
    k0_round_w<<<DF / 32, 32>>>(W);
    k1_deg<<<NN, 256>>>(A);
    dim3 g2(NN / 128, DF / 128);
    k2_mma<<<g2, 256, SMEM_BYTES>>>();
    k3_streamk<<<NCTA3, 256, SMEM_BYTES>>>(A, out, Acopy);
}